// round 10
// baseline (speedup 1.0000x reference)
#include <cuda_runtime.h>
#include <math.h>

#define NN   512
#define DD   128
#define M_TOTAL 2048   // 4*512

// Scratch (device globals: no allocation allowed in kernel_launch)
__device__ float g_Pb[M_TOTAL * DD];  // x@W1 - x@W2 + bias
__device__ float g_Q [M_TOTAL * DD];  // x@W2

// ---------------- packed f32x2 helpers (Blackwell; NO packed max) ----------
typedef unsigned long long ull;

static __device__ __forceinline__ ull pk2(float a) {      // {a, a}
    ull r; unsigned ai = __float_as_uint(a);
    asm("mov.b64 %0, {%1, %1};" : "=l"(r) : "r"(ai));
    return r;
}
static __device__ __forceinline__ ull add2(ull a, ull b) {
    ull r; asm("add.rn.f32x2 %0, %1, %2;" : "=l"(r) : "l"(a), "l"(b));
    return r;
}
static __device__ __forceinline__ ull fma2(ull a, ull b, ull c) {
    ull r; asm("fma.rn.f32x2 %0, %1, %2, %3;" : "=l"(r) : "l"(a), "l"(b), "l"(c));
    return r;
}

union F4U2 { float4 f4; ull u[2]; };

static __device__ __forceinline__ float4 f4max(float4 a, float4 b) {
    float4 r;
    r.x = fmaxf(a.x, b.x); r.y = fmaxf(a.y, b.y);
    r.z = fmaxf(a.z, b.z); r.w = fmaxf(a.w, b.w);
    return r;
}

// ---------------- cp.async helpers ----------------
static __device__ __forceinline__ void cpasync16(unsigned dst, const void* src) {
    asm volatile("cp.async.cg.shared.global [%0], [%1], 16;"
                 :: "r"(dst), "l"(src));
}
#define CP_COMMIT() asm volatile("cp.async.commit_group;")
#define CP_WAIT(n)  asm volatile("cp.async.wait_group %0;" :: "n"(n))

// ---------------------------------------------------------------------------
// Kernel 1: fused dual GEMM, 4-row thread tiles, f32x2 FMAs.
//   A1 = x@W1 ; Q = x@W2 ; Pb = A1 - Q + bias (epilogue)
// grid 128 x 128 threads. Block = 16 rows; warp = 4 rows; lane = 4 cols.
// Per 4-k step: 8 batched W LDG.128 + 16 bcast LDS.64 + 64 FFMA2 (73% math).
// x pre-packed {x,x} in smem so no per-use MOV packing.
// ---------------------------------------------------------------------------
__global__
void ec_gemm_kernel(const float* __restrict__ x,
                    const float* __restrict__ W,
                    const float* __restrict__ bias) {
    __shared__ ull xsp[16 * DD];     // 16 KB: {x,x} per (row, k)

    const int tid  = threadIdx.x;
    const int w    = tid >> 5;
    const int lane = tid & 31;
    const int rowBase = blockIdx.x * 16;

    // load & pack x tile: 16 rows x 128 k = 512 float4
    {
        const float4* x4 = (const float4*)(x + (size_t)rowBase * DD);
#pragma unroll
        for (int t = 0; t < 4; ++t) {
            const int idx = tid + t * 128;
            const float4 f = __ldg(&x4[idx]);
            xsp[idx * 4 + 0] = pk2(f.x);
            xsp[idx * 4 + 1] = pk2(f.y);
            xsp[idx * 4 + 2] = pk2(f.z);
            xsp[idx * 4 + 3] = pk2(f.w);
        }
    }
    __syncthreads();

    ull a1[4][2], qq[4][2];
#pragma unroll
    for (int r = 0; r < 4; ++r) {
        a1[r][0] = a1[r][1] = 0ull;
        qq[r][0] = qq[r][1] = 0ull;
    }

    const float4* __restrict__ W4 = (const float4*)W;
    const ull* xrow = &xsp[(w * 4) * DD];   // 4 consecutive rows, stride DD

    for (int kc = 0; kc < DD; kc += 4) {
        F4U2 w1[4], w2[4];
#pragma unroll
        for (int u = 0; u < 4; ++u) {       // 8 batched LDG.128 (MLP=8)
            w1[u].f4 = __ldg(&W4[(kc + u) * 32 + lane]);
            w2[u].f4 = __ldg(&W4[(kc + u + DD) * 32 + lane]);
        }
#pragma unroll
        for (int u = 0; u < 4; ++u) {
#pragma unroll
            for (int r = 0; r < 4; ++r) {
                const ull xp = xrow[r * DD + kc + u];   // LDS.64 broadcast
                a1[r][0] = fma2(xp, w1[u].u[0], a1[r][0]);
                a1[r][1] = fma2(xp, w1[u].u[1], a1[r][1]);
                qq[r][0] = fma2(xp, w2[u].u[0], qq[r][0]);
                qq[r][1] = fma2(xp, w2[u].u[1], qq[r][1]);
            }
        }
    }

    const float4 b4 = __ldg(&((const float4*)bias)[lane]);
#pragma unroll
    for (int r = 0; r < 4; ++r) {
        F4U2 A, Q;
        A.u[0] = a1[r][0]; A.u[1] = a1[r][1];
        Q.u[0] = qq[r][0]; Q.u[1] = qq[r][1];
        float4 P;
        P.x = (A.f4.x - Q.f4.x) + b4.x;
        P.y = (A.f4.y - Q.f4.y) + b4.y;
        P.z = (A.f4.z - Q.f4.z) + b4.z;
        P.w = (A.f4.w - Q.f4.w) + b4.w;
        const int m = rowBase + w * 4 + r;
        ((float4*)g_Pb)[(size_t)m * 32 + lane] = P;
        ((float4*)g_Q )[(size_t)m * 32 + lane] = Q.f4;
    }
}

// ---------------------------------------------------------------------------
// Kernel 2: dense masked max, 8-row blocks (90% math fraction).
//   out[b,i,o] = max(0, Pb[b,i,o] + max_j (Q[b,j,o] + m[i,j]))
// grid 256 x 256 threads (8 warps); block = 8 i-rows. 64 KB dyn smem:
//   qbuf[2][32*32] f4 (32 KB) + mpack[512][8] ull (32 KB) -> 3 blocks/SM.
// 16 chunks of 32 j, cp.async double-buffered. Warp w: j = w*4..w*4+3 per
// chunk for all 8 rows. Per j: 1 q LDS.128 + 4 mask LDS.128 + 16 FADD2
// + 32 FMNMX. Regs ~62 (no spill at 85-reg cap).
// ---------------------------------------------------------------------------
__global__ __launch_bounds__(256, 3)
void ec_maxred_kernel(const float* __restrict__ adj,
                      float* __restrict__ out) {
    extern __shared__ char dsm[];
    float4* qbuf = (float4*)dsm;                          // [2][1024]
    ull (*mpack)[8] = (ull (*)[8])(dsm + 32768);          // [512][8]

    const int tid  = threadIdx.x;
    const int w    = tid >> 5;
    const int lane = tid & 31;
    const int i0   = blockIdx.x * 8;     // first global row (b*NN + i)
    const int b    = i0 >> 9;

    const float4* __restrict__ Qb4 = ((const float4*)g_Q) + (size_t)b * NN * 32;

    // ---- stage chunk 0 (async) ----
    {
        unsigned dst0 = (unsigned)__cvta_generic_to_shared(qbuf);
#pragma unroll
        for (int t = 0; t < 4; ++t) {
            const int idx = tid + t * 256;
            cpasync16(dst0 + idx * 16, Qb4 + idx);
        }
        CP_COMMIT();
    }

    // ---- pre-pack ALL masks (8 rows x 512 j) while chunk 0 is in flight ----
    {
        const int pr = tid >> 5;          // row 0..7
        const int pj = (tid & 31) * 16;   // j base, 16 per thread
        const float4* arow4 =
            (const float4*)(adj + (size_t)(i0 + pr) * NN + pj);
#pragma unroll
        for (int t = 0; t < 4; ++t) {
            const float4 a = __ldg(arow4 + t);
            mpack[pj + t * 4 + 0][pr] = pk2(fmaf(a.x, 1e38f, -1e38f));
            mpack[pj + t * 4 + 1][pr] = pk2(fmaf(a.y, 1e38f, -1e38f));
            mpack[pj + t * 4 + 2][pr] = pk2(fmaf(a.z, 1e38f, -1e38f));
            mpack[pj + t * 4 + 3][pr] = pk2(fmaf(a.w, 1e38f, -1e38f));
        }
    }

    float4 acc[8];
#pragma unroll
    for (int r = 0; r < 8; ++r)
        acc[r] = make_float4(-3.0e38f, -3.0e38f, -3.0e38f, -3.0e38f);

    for (int c = 0; c < 16; ++c) {
        if (c < 15) {     // stage next chunk into the other buffer
            unsigned dst = (unsigned)__cvta_generic_to_shared(
                               qbuf + ((c + 1) & 1) * 1024);
#pragma unroll
            for (int t = 0; t < 4; ++t) {
                const int idx = tid + t * 256;
                cpasync16(dst + idx * 16, Qb4 + (c + 1) * 1024 + idx);
            }
            CP_COMMIT();
            CP_WAIT(1);   // chunk c arrived
        } else {
            CP_WAIT(0);
        }
        __syncthreads();

        const float4* qc = qbuf + (c & 1) * 1024;
        const int jb = w * 4;
#pragma unroll
        for (int u = 0; u < 4; ++u) {
            const int jl = jb + u;
            const int jg = c * 32 + jl;
            F4U2 q;
            q.f4 = qc[jl * 32 + lane];

            const ulonglong2 m01 = *(const ulonglong2*)&mpack[jg][0];
            const ulonglong2 m23 = *(const ulonglong2*)&mpack[jg][2];
            const ulonglong2 m45 = *(const ulonglong2*)&mpack[jg][4];
            const ulonglong2 m67 = *(const ulonglong2*)&mpack[jg][6];

#define MROW2(ra, rb, mm2) {                                      \
            F4U2 ta, tb;                                          \
            ta.u[0] = add2(q.u[0], (mm2).x);                      \
            ta.u[1] = add2(q.u[1], (mm2).x);                      \
            tb.u[0] = add2(q.u[0], (mm2).y);                      \
            tb.u[1] = add2(q.u[1], (mm2).y);                      \
            acc[ra] = f4max(acc[ra], ta.f4);                      \
            acc[rb] = f4max(acc[rb], tb.f4); }

            MROW2(0, 1, m01)
            MROW2(2, 3, m23)
            MROW2(4, 5, m45)
            MROW2(6, 7, m67)
#undef MROW2
        }
        __syncthreads();   // before next stage overwrites buffer (c+1)&1
    }

    // ---- reduction: 8 warp-partials per row (reuse qbuf = 32 KB) ----
    float4 (*buf)[8][32] = (float4 (*)[8][32])qbuf;

#pragma unroll
    for (int r = 0; r < 8; ++r) buf[w][r][lane] = acc[r];
    __syncthreads();

    // warp w finalizes row i0 + w
    {
        float4 v = buf[0][w][lane];
#pragma unroll
        for (int k = 1; k < 8; ++k) v = f4max(v, buf[k][w][lane]);

        const float4 p = __ldg(&((const float4*)g_Pb)[(size_t)(i0 + w) * 32 + lane]);
        float4 o;
        o.x = fmaxf(0.f, p.x + v.x);
        o.y = fmaxf(0.f, p.y + v.y);
        o.z = fmaxf(0.f, p.z + v.z);
        o.w = fmaxf(0.f, p.w + v.w);
        ((float4*)out)[(size_t)(i0 + w) * 32 + lane] = o;
    }
}

// ---------------------------------------------------------------------------
extern "C" void kernel_launch(void* const* d_in, const int* in_sizes, int n_in,
                              void* d_out, int out_size) {
    const float* x    = (const float*)d_in[0];   // (4,512,128)
    const float* adj  = (const float*)d_in[1];   // (4,512,512)
    const float* W    = (const float*)d_in[2];   // (256,128)
    const float* bias = (const float*)d_in[3];   // (128,)
    float*       out  = (float*)d_out;           // (4,512,128)

    const int DSM = 32768 + 32768;               // 64 KB dynamic smem
    cudaFuncSetAttribute(ec_maxred_kernel,
                         cudaFuncAttributeMaxDynamicSharedMemorySize, DSM);

    ec_gemm_kernel<<<M_TOTAL / 16, 128>>>(x, W, bias);
    ec_maxred_kernel<<<M_TOTAL / 8, 256, DSM>>>(adj, out);
}

// round 11
// speedup vs baseline: 1.3337x; 1.3337x over previous
#include <cuda_runtime.h>
#include <math.h>

#define NN   512
#define DD   128
#define M_TOTAL 2048   // 4*512

// Scratch (device globals: no allocation allowed in kernel_launch)
__device__ float g_Pb[M_TOTAL * DD];  // x@W1 - x@W2 + bias
__device__ float g_Q [M_TOTAL * DD];  // x@W2

// ---------------- packed f32x2 helpers (Blackwell; NO packed max) ----------
typedef unsigned long long ull;

static __device__ __forceinline__ ull pk2(float a) {      // {a, a}
    ull r; unsigned ai = __float_as_uint(a);
    asm("mov.b64 %0, {%1, %1};" : "=l"(r) : "r"(ai));
    return r;
}
static __device__ __forceinline__ ull add2(ull a, ull b) {
    ull r; asm("add.rn.f32x2 %0, %1, %2;" : "=l"(r) : "l"(a), "l"(b));
    return r;
}
static __device__ __forceinline__ ull fma2(ull a, ull b, ull c) {
    ull r; asm("fma.rn.f32x2 %0, %1, %2, %3;" : "=l"(r) : "l"(a), "l"(b), "l"(c));
    return r;
}

union F4U2 { float4 f4; ull u[2]; };
union U2F2 { ull u; float2 f2; };

static __device__ __forceinline__ float4 f4max(float4 a, float4 b) {
    float4 r;
    r.x = fmaxf(a.x, b.x); r.y = fmaxf(a.y, b.y);
    r.z = fmaxf(a.z, b.z); r.w = fmaxf(a.w, b.w);
    return r;
}

// ---------------- cp.async helpers ----------------
static __device__ __forceinline__ void cpasync16(unsigned dst, const void* src) {
    asm volatile("cp.async.cg.shared.global [%0], [%1], 16;"
                 :: "r"(dst), "l"(src));
}
#define CP_COMMIT() asm volatile("cp.async.commit_group;")
#define CP_WAIT(n)  asm volatile("cp.async.wait_group %0;" :: "n"(n))

// ---------------------------------------------------------------------------
// Kernel 1: fused dual GEMM, W STAGED IN SMEM (W L2 traffic: 16 MB total,
// 8x less than reading W per-warp).
//   A1 = x@W1 ; Q = x@W2 ; Pb = A1 - Q + bias (epilogue)
// grid 128 x 256 threads. Block = 16 rows. Warp = 4 rows x 64 cols:
//   warp w -> rows (w>>1)*4.., col-half (w&1). Lane owns 1 f32x2 col-pair
//   per matrix. Per k: 2 LDS.64 (W) + 4 bcast LDS.64 (x) + 8 FFMA2.
// W chunks of 16 k double-buffered via cp.async.
// ---------------------------------------------------------------------------
__global__ __launch_bounds__(256)
void ec_gemm_kernel(const float* __restrict__ x,
                    const float* __restrict__ W,
                    const float* __restrict__ bias) {
    __shared__ ull xs[16 * DD];        // 16 KB: {x,x} per (row, k)
    __shared__ ull wb[2][16 * 128];    // 32 KB: per k: W1 64 pairs | W2 64 pairs

    const int tid  = threadIdx.x;
    const int w    = tid >> 5;
    const int lane = tid & 31;
    const int rowBase = blockIdx.x * 16;

    const int ch  = w & 1;             // col half (0/1)
    const int r0  = (w >> 1) * 4;      // first of 4 local rows
    const int cp  = ch * 32 + lane;    // col-pair index 0..63

    const float4* __restrict__ W4 = (const float4*)W;

    // stage W chunk 0 (async) while packing x
    {
        unsigned dst = (unsigned)__cvta_generic_to_shared(&wb[0][0]);
#pragma unroll
        for (int t = 0; t < 4; ++t) {
            const int idx = tid + t * 256;          // 0..1023 float4
            const int half = idx >> 9;              // 0: W1, 1: W2
            const int i2 = idx & 511;
            const int k = i2 >> 5, l = i2 & 31;
            // dst float4 index within chunk: k*64 + half*32 + l
            cpasync16(dst + (k * 64 + half * 32 + l) * 16,
                      W4 + (size_t)(k + half * DD) * 32 + l);
        }
        CP_COMMIT();
    }

    // load & pack x tile: 16 rows x 128 k = 512 float4
    {
        const float4* x4 = (const float4*)(x + (size_t)rowBase * DD);
#pragma unroll
        for (int t = 0; t < 2; ++t) {
            const int idx = tid + t * 256;
            const float4 f = __ldg(&x4[idx]);
            xs[idx * 4 + 0] = pk2(f.x);
            xs[idx * 4 + 1] = pk2(f.y);
            xs[idx * 4 + 2] = pk2(f.z);
            xs[idx * 4 + 3] = pk2(f.w);
        }
    }

    ull a1[4], qq[4];
#pragma unroll
    for (int r = 0; r < 4; ++r) { a1[r] = 0ull; qq[r] = 0ull; }

    for (int c = 0; c < 8; ++c) {
        const int kc = c * 16;
        if (c < 7) {       // stage next chunk
            unsigned dst = (unsigned)__cvta_generic_to_shared(&wb[(c + 1) & 1][0]);
            const int kn = kc + 16;
#pragma unroll
            for (int t = 0; t < 4; ++t) {
                const int idx = tid + t * 256;
                const int half = idx >> 9;
                const int i2 = idx & 511;
                const int k = i2 >> 5, l = i2 & 31;
                cpasync16(dst + (k * 64 + half * 32 + l) * 16,
                          W4 + (size_t)(kn + k + half * DD) * 32 + l);
            }
            CP_COMMIT();
            CP_WAIT(1);
        } else {
            CP_WAIT(0);
        }
        __syncthreads();

        const ull* wc = &wb[c & 1][0];
#pragma unroll
        for (int k = 0; k < 16; ++k) {
            const ull w1 = wc[k * 128 + cp];        // LDS.64, conflict-free
            const ull w2 = wc[k * 128 + 64 + cp];
#pragma unroll
            for (int r = 0; r < 4; ++r) {
                const ull xp = xs[(r0 + r) * DD + kc + k];   // broadcast
                a1[r] = fma2(xp, w1, a1[r]);
                qq[r] = fma2(xp, w2, qq[r]);
            }
        }
        __syncthreads();   // before overwriting buffer (c+1)&1
    }

    const float2 b2 = __ldg(&((const float2*)bias)[cp]);
#pragma unroll
    for (int r = 0; r < 4; ++r) {
        U2F2 A, Q;
        A.u = a1[r]; Q.u = qq[r];
        float2 P;
        P.x = (A.f2.x - Q.f2.x) + b2.x;
        P.y = (A.f2.y - Q.f2.y) + b2.y;
        const int m = rowBase + r0 + r;
        ((float2*)g_Pb)[(size_t)m * 64 + cp] = P;
        ((float2*)g_Q )[(size_t)m * 64 + cp] = Q.f2;
    }
}

// ---------------------------------------------------------------------------
// Kernel 2: dense masked max, DIRECT-LDG q (no staging, no in-loop barriers).
//   out[b,i,o] = max(0, Pb[b,i,o] + max_j (Q[b,j,o] + m[i,j]))
//   m[i,j] = 0 if adj else -1e38 (exact masking), pre-packed {m,m} once.
// grid 256 x 512 threads (16 warps); block = 8 i-rows. Warp w owns 32
// contiguous j; q loaded via LDG with 1-deep prefetch (L2 latency hidden by
// 48 math instrs/j x 8 warps/SMSP). 32 KB static smem (masks, reused for
// the final reduction).
// ---------------------------------------------------------------------------
__global__ __launch_bounds__(512, 2)
void ec_maxred_kernel(const float* __restrict__ adj,
                      float* __restrict__ out) {
    __shared__ ull pool[4096];           // 32 KB: mpack[512][8], then red bufs

    const int tid  = threadIdx.x;
    const int w    = tid >> 5;
    const int lane = tid & 31;
    const int i0   = blockIdx.x * 8;     // first global row (b*NN + i)
    const int b    = i0 >> 9;

    // ---- pre-pack masks (8 rows x 512 j), [j][row] layout ----
    {
        const int pr = tid >> 6;          // row 0..7
        const int pj = (tid & 63) * 8;    // j base, 8 per thread
        const float4* arow4 =
            (const float4*)(adj + (size_t)(i0 + pr) * NN + pj);
#pragma unroll
        for (int t = 0; t < 2; ++t) {
            const float4 a = __ldg(arow4 + t);
            pool[(pj + t * 4 + 0) * 8 + pr] = pk2(fmaf(a.x, 1e38f, -1e38f));
            pool[(pj + t * 4 + 1) * 8 + pr] = pk2(fmaf(a.y, 1e38f, -1e38f));
            pool[(pj + t * 4 + 2) * 8 + pr] = pk2(fmaf(a.z, 1e38f, -1e38f));
            pool[(pj + t * 4 + 3) * 8 + pr] = pk2(fmaf(a.w, 1e38f, -1e38f));
        }
    }
    __syncthreads();

    const float4* __restrict__ Qb4 =
        ((const float4*)g_Q) + (size_t)b * NN * 32 + lane;

    float4 acc[8];
#pragma unroll
    for (int r = 0; r < 8; ++r)
        acc[r] = make_float4(-3.0e38f, -3.0e38f, -3.0e38f, -3.0e38f);

    const int j0 = w * 32;               // this warp's 32 contiguous j
    float4 qn = __ldg(Qb4 + (size_t)j0 * 32);

#pragma unroll 4
    for (int t = 0; t < 32; ++t) {
        F4U2 q;
        q.f4 = qn;
        if (t < 31) qn = __ldg(Qb4 + (size_t)(j0 + t + 1) * 32);

        const ull* mj = &pool[(j0 + t) * 8];
        const ulonglong2 m01 = *(const ulonglong2*)(mj + 0);
        const ulonglong2 m23 = *(const ulonglong2*)(mj + 2);
        const ulonglong2 m45 = *(const ulonglong2*)(mj + 4);
        const ulonglong2 m67 = *(const ulonglong2*)(mj + 6);

#define MROW2(ra, rb, mm2) {                                      \
        F4U2 ta, tb;                                              \
        ta.u[0] = add2(q.u[0], (mm2).x);                          \
        ta.u[1] = add2(q.u[1], (mm2).x);                          \
        tb.u[0] = add2(q.u[0], (mm2).y);                          \
        tb.u[1] = add2(q.u[1], (mm2).y);                          \
        acc[ra] = f4max(acc[ra], ta.f4);                          \
        acc[rb] = f4max(acc[rb], tb.f4); }

        MROW2(0, 1, m01)
        MROW2(2, 3, m23)
        MROW2(4, 5, m45)
        MROW2(6, 7, m67)
#undef MROW2
    }

    // ---- tree reduction 16 -> 1 warps, reusing pool (8 slots x 4 KB) ----
    __syncthreads();                     // all mask reads done; reuse pool
    float4* red = (float4*)pool;         // red[slot*256 + r*32 + lane]

#define WRITE_ACC(s) {                                            \
    _Pragma("unroll")                                             \
    for (int r = 0; r < 8; ++r) red[(s) * 256 + r * 32 + lane] = acc[r]; }
#define MERGE_ACC(s) {                                            \
    _Pragma("unroll")                                             \
    for (int r = 0; r < 8; ++r)                                   \
        acc[r] = f4max(acc[r], red[(s) * 256 + r * 32 + lane]); }

    if (w >= 8) WRITE_ACC(w - 8);
    __syncthreads();
    if (w < 8) MERGE_ACC(w);
    __syncthreads();
    if (w >= 4 && w < 8) WRITE_ACC(w - 4);
    __syncthreads();
    if (w < 4) MERGE_ACC(w);
    __syncthreads();
    if (w >= 2 && w < 4) WRITE_ACC(w - 2);
    __syncthreads();
    if (w < 2) MERGE_ACC(w);
    __syncthreads();
    if (w == 1) WRITE_ACC(0);
    __syncthreads();

    if (w == 0) {
        MERGE_ACC(0);
        const float4* __restrict__ P4 = (const float4*)g_Pb;
        float4* __restrict__ O4 = (float4*)out;
#pragma unroll
        for (int r = 0; r < 8; ++r) {
            const float4 p = __ldg(&P4[(size_t)(i0 + r) * 32 + lane]);
            float4 o;
            o.x = fmaxf(0.f, p.x + acc[r].x);
            o.y = fmaxf(0.f, p.y + acc[r].y);
            o.z = fmaxf(0.f, p.z + acc[r].z);
            o.w = fmaxf(0.f, p.w + acc[r].w);
            O4[(size_t)(i0 + r) * 32 + lane] = o;
        }
    }
#undef WRITE_ACC
#undef MERGE_ACC
}

// ---------------------------------------------------------------------------
extern "C" void kernel_launch(void* const* d_in, const int* in_sizes, int n_in,
                              void* d_out, int out_size) {
    const float* x    = (const float*)d_in[0];   // (4,512,128)
    const float* adj  = (const float*)d_in[1];   // (4,512,512)
    const float* W    = (const float*)d_in[2];   // (256,128)
    const float* bias = (const float*)d_in[3];   // (128,)
    float*       out  = (float*)d_out;           // (4,512,128)

    ec_gemm_kernel<<<M_TOTAL / 16, 256>>>(x, W, bias);
    ec_maxred_kernel<<<M_TOTAL / 8, 512>>>(adj, out);
}

// round 12
// speedup vs baseline: 1.3518x; 1.0136x over previous
#include <cuda_runtime.h>
#include <math.h>

#define NN   512
#define DD   128
#define M_TOTAL 2048   // 4*512

// Scratch (device globals: no allocation allowed in kernel_launch)
__device__ float g_Pb[M_TOTAL * DD];  // x@W1 - x@W2 + bias
__device__ float g_Q [M_TOTAL * DD];  // x@W2

// ---------------- packed f32x2 helpers (Blackwell; NO packed max) ----------
typedef unsigned long long ull;

static __device__ __forceinline__ ull pk2(float a) {      // {a, a}
    ull r; unsigned ai = __float_as_uint(a);
    asm("mov.b64 %0, {%1, %1};" : "=l"(r) : "r"(ai));
    return r;
}
static __device__ __forceinline__ ull add2(ull a, ull b) {
    ull r; asm("add.rn.f32x2 %0, %1, %2;" : "=l"(r) : "l"(a), "l"(b));
    return r;
}
static __device__ __forceinline__ ull fma2(ull a, ull b, ull c) {
    ull r; asm("fma.rn.f32x2 %0, %1, %2, %3;" : "=l"(r) : "l"(a), "l"(b), "l"(c));
    return r;
}

union U2F2 { ull u; float2 f2; };

// ---------------- cp.async helpers ----------------
static __device__ __forceinline__ void cpasync16(unsigned dst, const void* src) {
    asm volatile("cp.async.cg.shared.global [%0], [%1], 16;"
                 :: "r"(dst), "l"(src));
}
#define CP_COMMIT() asm volatile("cp.async.commit_group;")
#define CP_WAIT(n)  asm volatile("cp.async.wait_group %0;" :: "n"(n))

// ---------------------------------------------------------------------------
// Kernel 1: fused dual GEMM, W staged in SMEM (16 MB total W L2 traffic).
//   A1 = x@W1 ; Q = x@W2 ; Pb = A1 - Q + bias (epilogue)
// grid 128 x 256 threads. Block = 16 rows. Warp = 4 rows x 64 cols.
// ---------------------------------------------------------------------------
__global__ __launch_bounds__(256)
void ec_gemm_kernel(const float* __restrict__ x,
                    const float* __restrict__ W,
                    const float* __restrict__ bias) {
    __shared__ ull xs[16 * DD];        // 16 KB: {x,x} per (row, k)
    __shared__ ull wb[2][16 * 128];    // 32 KB: per k: W1 64 pairs | W2 64 pairs

    const int tid  = threadIdx.x;
    const int w    = tid >> 5;
    const int lane = tid & 31;
    const int rowBase = blockIdx.x * 16;

    const int ch  = w & 1;             // col half (0/1)
    const int r0  = (w >> 1) * 4;      // first of 4 local rows
    const int cp  = ch * 32 + lane;    // col-pair index 0..63

    const float4* __restrict__ W4 = (const float4*)W;

    // stage W chunk 0 (async) while packing x
    {
        unsigned dst = (unsigned)__cvta_generic_to_shared(&wb[0][0]);
#pragma unroll
        for (int t = 0; t < 4; ++t) {
            const int idx = tid + t * 256;          // 0..1023 float4
            const int half = idx >> 9;              // 0: W1, 1: W2
            const int i2 = idx & 511;
            const int k = i2 >> 5, l = i2 & 31;
            cpasync16(dst + (k * 64 + half * 32 + l) * 16,
                      W4 + (size_t)(k + half * DD) * 32 + l);
        }
        CP_COMMIT();
    }

    // load & pack x tile: 16 rows x 128 k = 512 float4
    {
        const float4* x4 = (const float4*)(x + (size_t)rowBase * DD);
#pragma unroll
        for (int t = 0; t < 2; ++t) {
            const int idx = tid + t * 256;
            const float4 f = __ldg(&x4[idx]);
            xs[idx * 4 + 0] = pk2(f.x);
            xs[idx * 4 + 1] = pk2(f.y);
            xs[idx * 4 + 2] = pk2(f.z);
            xs[idx * 4 + 3] = pk2(f.w);
        }
    }

    ull a1[4], qq[4];
#pragma unroll
    for (int r = 0; r < 4; ++r) { a1[r] = 0ull; qq[r] = 0ull; }

    for (int c = 0; c < 8; ++c) {
        const int kc = c * 16;
        if (c < 7) {       // stage next chunk
            unsigned dst = (unsigned)__cvta_generic_to_shared(&wb[(c + 1) & 1][0]);
            const int kn = kc + 16;
#pragma unroll
            for (int t = 0; t < 4; ++t) {
                const int idx = tid + t * 256;
                const int half = idx >> 9;
                const int i2 = idx & 511;
                const int k = i2 >> 5, l = i2 & 31;
                cpasync16(dst + (k * 64 + half * 32 + l) * 16,
                          W4 + (size_t)(kn + k + half * DD) * 32 + l);
            }
            CP_COMMIT();
            CP_WAIT(1);
        } else {
            CP_WAIT(0);
        }
        __syncthreads();

        const ull* wc = &wb[c & 1][0];
#pragma unroll
        for (int k = 0; k < 16; ++k) {
            const ull w1 = wc[k * 128 + cp];        // LDS.64, conflict-free
            const ull w2 = wc[k * 128 + 64 + cp];
#pragma unroll
            for (int r = 0; r < 4; ++r) {
                const ull xp = xs[(r0 + r) * DD + kc + k];   // broadcast
                a1[r] = fma2(xp, w1, a1[r]);
                qq[r] = fma2(xp, w2, qq[r]);
            }
        }
        __syncthreads();   // before overwriting buffer (c+1)&1
    }

    const float2 b2 = __ldg(&((const float2*)bias)[cp]);
#pragma unroll
    for (int r = 0; r < 4; ++r) {
        U2F2 A, Q;
        A.u = a1[r]; Q.u = qq[r];
        float2 P;
        P.x = (A.f2.x - Q.f2.x) + b2.x;
        P.y = (A.f2.y - Q.f2.y) + b2.y;
        const int m = rowBase + r0 + r;
        ((float2*)g_Pb)[(size_t)m * 64 + cp] = P;
        ((float2*)g_Q )[(size_t)m * 64 + cp] = Q.f2;
    }
}

// ---------------------------------------------------------------------------
// Kernel 2: dense masked max, float2-per-lane (NO SPILLS: ~40 live regs).
//   out[b,i,o] = max(0, Pb[b,i,o] + max_j (Q[b,j,o] + m[i,j]))
// grid 256 x 512 threads (16 warps); block = 8 i-rows.
// Warp = (j-group jg = w>>1 owning 64 j, o-half = w&1 owning 64 o as 32
// float2 lanes). Per j: 1 LDG.64 q + 4 bcast LDS.128 masks + 8 FADD2 +
// 16 FMNMX. launch_bounds(512,3) -> 42-reg cap, 3 blocks/SM, 48 warps/SM.
// 32 KB smem: mpack[512][8] ull, reused as reduction buffer.
// ---------------------------------------------------------------------------
__global__ __launch_bounds__(512, 3)
void ec_maxred_kernel(const float* __restrict__ adj,
                      float* __restrict__ out) {
    __shared__ ull pool[4096];           // 32 KB

    const int tid  = threadIdx.x;
    const int w    = tid >> 5;
    const int lane = tid & 31;
    const int i0   = blockIdx.x * 8;     // first global row (b*NN + i)
    const int b    = i0 >> 9;

    // ---- pre-pack masks (8 rows x 512 j), [j][row] ull layout ----
    // Thread map: r = tid & 7 (row), jbase = (tid >> 3) * 8. Lanes 0..7 have
    // consecutive r -> consecutive ull addresses: only 4-way STS conflict.
    {
        const int pr = tid & 7;
        const int pj = (tid >> 3) * 8;
        const float4* arow4 =
            (const float4*)(adj + (size_t)(i0 + pr) * NN + pj);
#pragma unroll
        for (int t = 0; t < 2; ++t) {
            const float4 a = __ldg(arow4 + t);
            pool[(pj + t * 4 + 0) * 8 + pr] = pk2(fmaf(a.x, 1e38f, -1e38f));
            pool[(pj + t * 4 + 1) * 8 + pr] = pk2(fmaf(a.y, 1e38f, -1e38f));
            pool[(pj + t * 4 + 2) * 8 + pr] = pk2(fmaf(a.z, 1e38f, -1e38f));
            pool[(pj + t * 4 + 3) * 8 + pr] = pk2(fmaf(a.w, 1e38f, -1e38f));
        }
    }
    __syncthreads();

    const int half = w & 1;              // o-half
    const int jg   = w >> 1;             // j-group (64 j)
    const int cp   = half * 32 + lane;   // col-pair 0..63
    const int j0   = jg * 64;

    // Q as float2 words: row j = 64 ull
    const ull* __restrict__ Qb2 = ((const ull*)g_Q) + (size_t)b * NN * 64 + cp;

    U2F2 acc[8];
#pragma unroll
    for (int r = 0; r < 8; ++r) { acc[r].f2.x = -3.0e38f; acc[r].f2.y = -3.0e38f; }

    // 2-deep prefetch of q
    ull qa = __ldg(Qb2 + (size_t)j0 * 64);
    ull qb = __ldg(Qb2 + (size_t)(j0 + 1) * 64);

#pragma unroll 4
    for (int t = 0; t < 64; ++t) {
        const ull q = qa;
        qa = qb;
        if (t < 62) qb = __ldg(Qb2 + (size_t)(j0 + t + 2) * 64);

        const ull* mj = &pool[(j0 + t) * 8];
        const ulonglong2 m01 = *(const ulonglong2*)(mj + 0);
        const ulonglong2 m23 = *(const ulonglong2*)(mj + 2);
        const ulonglong2 m45 = *(const ulonglong2*)(mj + 4);
        const ulonglong2 m67 = *(const ulonglong2*)(mj + 6);

#define MROW(r, mm) {                                             \
        U2F2 tv; tv.u = add2(q, mm);                              \
        acc[r].f2.x = fmaxf(acc[r].f2.x, tv.f2.x);                \
        acc[r].f2.y = fmaxf(acc[r].f2.y, tv.f2.y); }

        MROW(0, m01.x) MROW(1, m01.y)
        MROW(2, m23.x) MROW(3, m23.y)
        MROW(4, m45.x) MROW(5, m45.y)
        MROW(6, m67.x) MROW(7, m67.y)
#undef MROW
    }

    // ---- reduction: merge 8 j-group warps per o-half (reuse pool) ----
    __syncthreads();                     // all mask reads done
    // red slot for warp w: pool[w*256 + r*32 + lane]
#pragma unroll
    for (int r = 0; r < 8; ++r) pool[w * 256 + r * 32 + lane] = acc[r].u;
    __syncthreads();

    if (w < 2) {                         // warp h = w finalizes o-half h
        const int h = w;
        const ull* __restrict__ Pb2 = (const ull*)g_Pb;
        ull* __restrict__ O2 = (ull*)out;
#pragma unroll
        for (int r = 0; r < 8; ++r) {
            U2F2 v; v.u = pool[h * 256 + r * 32 + lane];   // jg=0 partial
#pragma unroll
            for (int g = 1; g < 8; ++g) {
                U2F2 t2; t2.u = pool[(g * 2 + h) * 256 + r * 32 + lane];
                v.f2.x = fmaxf(v.f2.x, t2.f2.x);
                v.f2.y = fmaxf(v.f2.y, t2.f2.y);
            }
            const int hc = h * 32 + lane;
            U2F2 p; p.u = __ldg(&Pb2[(size_t)(i0 + r) * 64 + hc]);
            U2F2 o;
            o.f2.x = fmaxf(0.f, p.f2.x + v.f2.x);
            o.f2.y = fmaxf(0.f, p.f2.y + v.f2.y);
            O2[(size_t)(i0 + r) * 64 + hc] = o.u;
        }
    }
}

// ---------------------------------------------------------------------------
extern "C" void kernel_launch(void* const* d_in, const int* in_sizes, int n_in,
                              void* d_out, int out_size) {
    const float* x    = (const float*)d_in[0];   // (4,512,128)
    const float* adj  = (const float*)d_in[1];   // (4,512,512)
    const float* W    = (const float*)d_in[2];   // (256,128)
    const float* bias = (const float*)d_in[3];   // (128,)
    float*       out  = (float*)d_out;           // (4,512,128)

    ec_gemm_kernel<<<M_TOTAL / 16, 256>>>(x, W, bias);
    ec_maxred_kernel<<<M_TOTAL / 8, 512>>>(adj, out);
}